// round 7
// baseline (speedup 1.0000x reference)
#include <cuda_runtime.h>

#define PB   128
#define PHW  256
#define HW   1024
#define BIMG 8
#define NPER 16
#define NB   128
#define NGRP 4
#define NBG  (NB / NGRP)          // 32 boxes per gather group

#define THREADS    384
#define DS_BLOCKS  128            // 128*384 = 49152 = PB*PB*3
#define GT_BLOCKS  (NGRP * PB)    // 512
#define ROWS_PER_CP 4
#define CP_BLOCKS  (BIMG * HW / ROWS_PER_CP)   // 2048
#define FN_BLOCKS  512            // 512*384 = 196608 = PHW*PHW*3
#define TOTAL_BLOCKS (DS_BLOCKS + GT_BLOCKS + CP_BLOCKS + FN_BLOCKS)

// sign-extend low 8 bits (aarch64 'char' is unsigned — never use bare char!)
#define SEXT8(x) (((int)((x) << 24)) >> 24)

// Scratch (device globals — no allocation allowed)
__device__ float g_small[PB * PB * 3];              // downsampled patch
__device__ float g_nr[NGRP][PB][PB * 3];            // non-rot gather partials
__device__ float g_rt[NGRP][PB][PB * 3];            // rot gather partials (transposed)
__device__ int   g_sync[2];                          // [0]=ds done, [1]=gather done

// ---------------------------------------------------------------------------
// Role: antialiased bilinear downsample 256->128 (JAX triangle taps
// {0.25,0.75,0.75,0.25}, per-dim edge renormalization).
// ---------------------------------------------------------------------------
__device__ void role_downsample(int bid, const float* __restrict__ patch) {
    int t = bid * THREADS + threadIdx.x;
    int c = t % 3;
    int j = (t / 3) % PB;
    int i = t / (3 * PB);

    const float w0[4] = {0.25f, 0.75f, 0.75f, 0.25f};
    int by = 2 * i - 1, bx = 2 * j - 1;
    float wy[4], wx[4], sy = 0.f, sx = 0.f;
#pragma unroll
    for (int u = 0; u < 4; u++) { int r = by + u; wy[u] = (r >= 0 && r < PHW) ? w0[u] : 0.f; sy += wy[u]; }
#pragma unroll
    for (int v = 0; v < 4; v++) { int q = bx + v; wx[v] = (q >= 0 && q < PHW) ? w0[v] : 0.f; sx += wx[v]; }

    float acc = 0.f;
#pragma unroll
    for (int u = 0; u < 4; u++) {
        if (wy[u] == 0.f) continue;
        int r = by + u;
        float rowacc = 0.f;
#pragma unroll
        for (int v = 0; v < 4; v++) {
            if (wx[v] == 0.f) continue;
            rowacc += wx[v] * __ldg(&patch[(r * PHW + (bx + v)) * 3 + c]);
        }
        acc += wy[u] * rowacc;
    }
    g_small[t] = acc / (sy * sx);

    __syncthreads();
    __threadfence();
    if (threadIdx.x == 0) atomicAdd(&g_sync[0], 1);
}

// ---------------------------------------------------------------------------
// Role: gradient gather + inverse transform (coalesced for rot and non-rot).
// ---------------------------------------------------------------------------
__device__ void role_gather(int gb, const float* __restrict__ grads,
                            const int* __restrict__ box_yx,
                            const int* __restrict__ dec) {
    __shared__ int s_y[NBG], s_x[NBG], s_d[NBG], s_b[NBG];
    int tid = threadIdx.x;
    int g = gb >> 7;
    int r = gb & 127;

    if (tid < NBG) {
        int box = g * NBG + tid;
        s_y[tid] = __ldg(&box_yx[box * 2]);
        s_x[tid] = __ldg(&box_yx[box * 2 + 1]);
        s_d[tid] = (__ldg(&dec[box * 3]) > 0 ? 1 : 0) |
                   (__ldg(&dec[box * 3 + 1]) > 0 ? 2 : 0) |
                   (__ldg(&dec[box * 3 + 2]) > 0 ? 4 : 0);
        s_b[tid] = box >> 4;
    }
    __syncthreads();

    int j = tid / 3;
    int c = tid - 3 * j;

    float acc_nr = 0.f;
    float acc_rt = 0.f;
#pragma unroll 8
    for (int k = 0; k < NBG; ++k) {
        int d = s_d[k];
        size_t base = (size_t)s_b[k] * (HW * HW * 3);
        if (d & 1) {
            int row = s_y[k] + ((d & 4) ? r : (PB - 1 - r));
            int col = s_x[k] + ((d & 2) ? (PB - 1 - j) : j);
            acc_rt += __ldg(&grads[base + ((size_t)row * HW + col) * 3 + c]);
        } else {
            int row = s_y[k] + ((d & 4) ? (PB - 1 - r) : r);
            int col = s_x[k] + ((d & 2) ? (PB - 1 - j) : j);
            acc_nr += __ldg(&grads[base + ((size_t)row * HW + col) * 3 + c]);
        }
    }
    g_nr[g][r][tid] = acc_nr;
    g_rt[g][r][tid] = acc_rt;

    __syncthreads();
    __threadfence();
    if (tid == 0) atomicAdd(&g_sync[1], 1);
}

// ---------------------------------------------------------------------------
// Role: fused copy + paste, 4 rows per block, chunked (4 quads at a time) to
// keep live registers low (occupancy!) while retaining MLP=4.
// ---------------------------------------------------------------------------
__device__ void role_copy(int cb, const float* __restrict__ images,
                          const int* __restrict__ box_yx, const int* __restrict__ dec,
                          float* __restrict__ out) {
    int b = cb >> 8;                     // 256 blocks per image
    int ybase = (cb & 255) * ROWS_PER_CP;
    int tid = threadIdx.x;

    __shared__ unsigned s_mask[ROWS_PER_CP];
    __shared__ int s_x0[NPER];
    __shared__ int s_y0[NPER];
    __shared__ int s_d[NPER];

    if (tid < 32) {
        int y0 = 0;
        if (tid < NPER) {
            int box = b * NPER + tid;
            y0 = __ldg(&box_yx[box * 2]);
            s_x0[tid] = __ldg(&box_yx[box * 2 + 1]);
            s_y0[tid] = y0;
            s_d[tid] = (__ldg(&dec[box * 3]) > 0 ? 1 : 0) |
                       (__ldg(&dec[box * 3 + 1]) > 0 ? 2 : 0) |
                       (__ldg(&dec[box * 3 + 2]) > 0 ? 4 : 0);
        }
#pragma unroll
        for (int r = 0; r < ROWS_PER_CP; r++) {
            int cov = (tid < NPER) && ((unsigned)(ybase + r - y0) < (unsigned)PB);
            unsigned m = __ballot_sync(0xFFFFFFFFu, cov) & 0xFFFFu;
            if (tid == 0) s_mask[r] = m;
        }
    }
    __syncthreads();

    size_t base4 = ((size_t)(b * HW + ybase)) * (HW * 3 / 4);
    const float4* src4 = (const float4*)images + base4;
    float4* dst4 = (float4*)out + base4;

    unsigned allmask = s_mask[0] | s_mask[1] | s_mask[2] | s_mask[3];

    if (allmask == 0) {
        // pure copy: two chunks of 4 float4 (MLP=4, low live regs)
#pragma unroll
        for (int h = 0; h < 2; h++) {
            float4 v[4];
#pragma unroll
            for (int k = 0; k < 4; k++) {
                int q = (h * 4 + k);
                v[k] = __ldcs(&src4[(q >> 1) * 768 + (q & 1) * THREADS + tid]);
            }
#pragma unroll
            for (int k = 0; k < 4; k++) {
                int q = (h * 4 + k);
                __stcs(&dst4[(q >> 1) * 768 + (q & 1) * THREADS + tid], v[k]);
            }
        }
        return;
    }

    // need patch: wait for downsample completion (fast after wave 1)
    if (tid == 0) {
        volatile int* p = &g_sync[0];
        while (*p < DS_BLOCKS) __nanosleep(64);
    }
    __syncthreads();

#pragma unroll
    for (int h = 0; h < 2; h++) {
        // Phase 1: resolve covering boxes for 4 quads (packed: ba | bb<<8)
        int pk[4];
#pragma unroll
        for (int k = 0; k < 4; k++) {
            int q = h * 4 + k;
            int row = q >> 1;
            int qq = (q & 1) * THREADS + tid;
            int pa = (qq * 4) / 3;
            int ba = -1, bb = -1;
            unsigned m = s_mask[row];
            while (m) {
                int n = 31 - __clz(m);
                m &= ~(1u << n);
                int x0 = s_x0[n];
                if (ba < 0 && (unsigned)(pa - x0) < (unsigned)PB) ba = n;
                if (bb < 0 && (unsigned)(pa + 1 - x0) < (unsigned)PB) bb = n;
                if (ba >= 0 && bb >= 0) break;
            }
            pk[k] = (ba & 0xFF) | ((bb & 0xFF) << 8);
        }

        // Phase 2: batched source loads (skip fully-pasted quads)
        float4 v[4];
#pragma unroll
        for (int k = 0; k < 4; k++) {
            int q = h * 4 + k;
            int ba = SEXT8(pk[k] & 0xFF);
            int bb = SEXT8((pk[k] >> 8) & 0xFF);
            if (ba < 0 || bb < 0)
                v[k] = __ldcs(&src4[(q >> 1) * 768 + (q & 1) * THREADS + tid]);
        }

        // Phase 3: compose + store
#pragma unroll
        for (int k = 0; k < 4; k++) {
            int q = h * 4 + k;
            int row = q >> 1;
            int qq = (q & 1) * THREADS + tid;
            int fo = qq * 4;
            int pa = fo / 3;
            int ba = SEXT8(pk[k] & 0xFF);
            int bb = SEXT8((pk[k] >> 8) & 0xFF);
            float* vf = (float*)&v[k];
            if (ba >= 0 || bb >= 0) {
                int yg = ybase + row;
#pragma unroll
                for (int e = 0; e < 4; e++) {
                    int fe = fo + e;
                    int px = fe / 3;
                    int box = (px == pa) ? ba : bb;
                    if (box < 0) continue;
                    int c = fe - 3 * px;
                    int rx = px - s_x0[box];
                    int ry = yg - s_y0[box];
                    int d = s_d[box];
                    int y2 = (d & 4) ? (PB - 1 - ry) : ry;
                    int x1 = (d & 2) ? (PB - 1 - rx) : rx;
                    int sy_ = (d & 1) ? x1 : y2;
                    int sx_ = (d & 1) ? (PB - 1 - y2) : x1;
                    vf[e] = g_small[(sy_ * PB + sx_) * 3 + c];
                }
            }
            __stcs(&dst4[(q >> 1) * 768 + (q & 1) * THREADS + tid], v[k]);
        }
    }
}

// ---------------------------------------------------------------------------
// Role: reduce gather partials + bilinear upsample 128->256 + analytic TV grad.
// ---------------------------------------------------------------------------
__device__ __forceinline__ float acc_at(int y, int x, int c) {
    float s = 0.f;
#pragma unroll
    for (int g = 0; g < NGRP; g++) {
        s += g_nr[g][y][x * 3 + c];
        s += g_rt[g][x][y * 3 + c];
    }
    return s;
}

__device__ void role_final(int fb, const float* __restrict__ patch,
                           float* __restrict__ agg) {
    if (threadIdx.x == 0) {
        volatile int* p = &g_sync[1];
        while (*p < GT_BLOCKS) __nanosleep(64);
    }
    __syncthreads();

    int t = fb * THREADS + threadIdx.x;
    int c = t % 3;
    int j = (t / 3) % PHW;
    int i = t / (PHW * 3);

    int ky = i >> 1, y0, y1; float wy0, wy1;
    if (i & 1) { y0 = ky;             y1 = min(ky + 1, PB - 1); wy0 = 0.75f; wy1 = 0.25f; }
    else       { y0 = max(ky - 1, 0); y1 = ky;                  wy0 = 0.25f; wy1 = 0.75f; }
    int kx = j >> 1, x0, x1; float wx0, wx1;
    if (j & 1) { x0 = kx;             x1 = min(kx + 1, PB - 1); wx0 = 0.75f; wx1 = 0.25f; }
    else       { x0 = max(kx - 1, 0); x1 = kx;                  wx0 = 0.25f; wx1 = 0.75f; }

    float v = wy0 * (wx0 * acc_at(y0, x0, c) + wx1 * acc_at(y0, x1, c))
            + wy1 * (wx0 * acc_at(y1, x0, c) + wx1 * acc_at(y1, x1, c));

    float pij = __ldg(&patch[(i * PHW + j) * 3 + c]);
    float a = (j < PHW - 1) ? (pij - __ldg(&patch[(i * PHW + j + 1) * 3 + c])) : 0.f;
    float bb = (i < PHW - 1) ? (pij - __ldg(&patch[((i + 1) * PHW + j) * 3 + c])) : 0.f;
    float g = (a + bb) * rsqrtf(a * a + bb * bb + 1e-12f);
    if (j > 0) {
        float pl = __ldg(&patch[(i * PHW + j - 1) * 3 + c]);
        float al = pl - pij;
        float bl = (i < PHW - 1) ? (pl - __ldg(&patch[((i + 1) * PHW + j - 1) * 3 + c])) : 0.f;
        g -= al * rsqrtf(al * al + bl * bl + 1e-12f);
    }
    if (i > 0) {
        float pu = __ldg(&patch[((i - 1) * PHW + j) * 3 + c]);
        float bu = pu - pij;
        float au = (j < PHW - 1) ? (pu - __ldg(&patch[((i - 1) * PHW + j + 1) * 3 + c])) : 0.f;
        g -= bu * rsqrtf(au * au + bu * bu + 1e-12f);
    }
    agg[t] = v + 0.5f * g;
}

// ---------------------------------------------------------------------------
__global__ void __launch_bounds__(THREADS, 4) k_mega(
        const float* __restrict__ images, const float* __restrict__ grads,
        const float* __restrict__ patch,
        const int* __restrict__ box_yx, const int* __restrict__ dec,
        float* __restrict__ out, float* __restrict__ agg) {
    int bid = blockIdx.x;
    if (bid < DS_BLOCKS) {
        role_downsample(bid, patch);
    } else if (bid < DS_BLOCKS + GT_BLOCKS) {
        role_gather(bid - DS_BLOCKS, grads, box_yx, dec);
    } else if (bid < DS_BLOCKS + GT_BLOCKS + CP_BLOCKS) {
        role_copy(bid - (DS_BLOCKS + GT_BLOCKS), images, box_yx, dec, out);
    } else {
        role_final(bid - (DS_BLOCKS + GT_BLOCKS + CP_BLOCKS), patch, agg);
    }
}

// ---------------------------------------------------------------------------
extern "C" void kernel_launch(void* const* d_in, const int* in_sizes, int n_in,
                              void* d_out, int out_size) {
    const float* images = (const float*)d_in[0];
    const float* grads  = (const float*)d_in[1];
    const float* patch  = (const float*)d_in[2];
    const int*   box_yx = (const int*)d_in[3];
    const int*   dec    = (const int*)d_in[4];

    float* out = (float*)d_out;
    size_t img_elems = (size_t)BIMG * HW * HW * 3;
    float* agg = out + img_elems;

    void* sptr = nullptr;
    cudaGetSymbolAddress(&sptr, g_sync);
    cudaMemsetAsync(sptr, 0, 2 * sizeof(int));

    k_mega<<<TOTAL_BLOCKS, THREADS>>>(images, grads, patch, box_yx, dec, out, agg);
}

// round 8
// speedup vs baseline: 1.0132x; 1.0132x over previous
#include <cuda_runtime.h>

#define PB   128
#define PHW  256
#define HW   1024
#define BIMG 8
#define NPER 16
#define NB   128
#define NGRP 4
#define NBG  (NB / NGRP)          // 32 boxes per gather group

#define THREADS    384
#define DS_BLOCKS  128            // 128*384 = 49152 = PB*PB*3
#define GT_BLOCKS  (NGRP * PB)    // 512
#define PS_BLOCKS  (NB * 4)       // 512: 4 blocks per box, 32 rows each
#define ROWS_PER_CP 4
#define CP_BLOCKS  (BIMG * HW / ROWS_PER_CP)   // 2048
#define FN_BLOCKS  512            // 512*384 = 196608 = PHW*PHW*3
#define TOTAL_BLOCKS (DS_BLOCKS + GT_BLOCKS + PS_BLOCKS + CP_BLOCKS + FN_BLOCKS)

// Scratch (device globals — no allocation allowed)
__device__ float g_small[PB * PB * 3];              // downsampled patch
__device__ float g_smallT[PB * PB * 3];             // transposed copy (coalesced rot reads)
__device__ float g_nr[NGRP][PB][PB * 3];            // non-rot gather partials
__device__ float g_rt[NGRP][PB][PB * 3];            // rot gather partials (transposed)
__device__ int   g_sync[2];                          // [0]=ds done, [1]=gather done

// ---------------------------------------------------------------------------
// Role: antialiased bilinear downsample 256->128 (JAX triangle taps
// {0.25,0.75,0.75,0.25}, per-dim edge renormalization). Writes g_small and
// its transpose.
// ---------------------------------------------------------------------------
__device__ void role_downsample(int bid, const float* __restrict__ patch) {
    int t = bid * THREADS + threadIdx.x;
    int c = t % 3;
    int j = (t / 3) % PB;
    int i = t / (3 * PB);

    const float w0[4] = {0.25f, 0.75f, 0.75f, 0.25f};
    int by = 2 * i - 1, bx = 2 * j - 1;
    float wy[4], wx[4], sy = 0.f, sx = 0.f;
#pragma unroll
    for (int u = 0; u < 4; u++) { int r = by + u; wy[u] = (r >= 0 && r < PHW) ? w0[u] : 0.f; sy += wy[u]; }
#pragma unroll
    for (int v = 0; v < 4; v++) { int q = bx + v; wx[v] = (q >= 0 && q < PHW) ? w0[v] : 0.f; sx += wx[v]; }

    float acc = 0.f;
#pragma unroll
    for (int u = 0; u < 4; u++) {
        if (wy[u] == 0.f) continue;
        int r = by + u;
        float rowacc = 0.f;
#pragma unroll
        for (int v = 0; v < 4; v++) {
            if (wx[v] == 0.f) continue;
            rowacc += wx[v] * __ldg(&patch[(r * PHW + (bx + v)) * 3 + c]);
        }
        acc += wy[u] * rowacc;
    }
    float val = acc / (sy * sx);
    g_small[t] = val;
    g_smallT[(j * PB + i) * 3 + c] = val;

    __syncthreads();
    __threadfence();
    if (threadIdx.x == 0) atomicAdd(&g_sync[0], 1);
}

// ---------------------------------------------------------------------------
// Role: gradient gather + inverse transform (coalesced for rot and non-rot).
// ---------------------------------------------------------------------------
__device__ void role_gather(int gb, const float* __restrict__ grads,
                            const int* __restrict__ box_yx,
                            const int* __restrict__ dec) {
    __shared__ int s_y[NBG], s_x[NBG], s_d[NBG], s_b[NBG];
    int tid = threadIdx.x;
    int g = gb >> 7;
    int r = gb & 127;

    if (tid < NBG) {
        int box = g * NBG + tid;
        s_y[tid] = __ldg(&box_yx[box * 2]);
        s_x[tid] = __ldg(&box_yx[box * 2 + 1]);
        s_d[tid] = (__ldg(&dec[box * 3]) > 0 ? 1 : 0) |
                   (__ldg(&dec[box * 3 + 1]) > 0 ? 2 : 0) |
                   (__ldg(&dec[box * 3 + 2]) > 0 ? 4 : 0);
        s_b[tid] = box >> 4;
    }
    __syncthreads();

    int j = tid / 3;
    int c = tid - 3 * j;

    float acc_nr = 0.f;
    float acc_rt = 0.f;
#pragma unroll 8
    for (int k = 0; k < NBG; ++k) {
        int d = s_d[k];
        size_t base = (size_t)s_b[k] * (HW * HW * 3);
        if (d & 1) {
            int row = s_y[k] + ((d & 4) ? r : (PB - 1 - r));
            int col = s_x[k] + ((d & 2) ? (PB - 1 - j) : j);
            acc_rt += __ldg(&grads[base + ((size_t)row * HW + col) * 3 + c]);
        } else {
            int row = s_y[k] + ((d & 4) ? (PB - 1 - r) : r);
            int col = s_x[k] + ((d & 2) ? (PB - 1 - j) : j);
            acc_nr += __ldg(&grads[base + ((size_t)row * HW + col) * 3 + c]);
        }
    }
    g_nr[g][r][tid] = acc_nr;
    g_rt[g][r][tid] = acc_rt;

    __syncthreads();
    __threadfence();
    if (tid == 0) atomicAdd(&g_sync[1], 1);
}

// ---------------------------------------------------------------------------
// Role: paste. 4 blocks per box, 32 rows each. Pure stores of the transformed
// tile; later-box-wins via a compacted overlap list (usually empty).
// ---------------------------------------------------------------------------
__device__ void role_paste(int pb_, const float* __restrict__ grads_unused,
                           const int* __restrict__ box_yx, const int* __restrict__ dec,
                           float* __restrict__ out) {
    int box = pb_ >> 2;
    int rbase = (pb_ & 3) * 32;
    int b = box >> 4;
    int n = box & 15;
    int tid = threadIdx.x;

    __shared__ int s_y0, s_x0, s_d;
    __shared__ int l_y[NPER], l_x[NPER];
    __shared__ int l_cnt;

    if (tid == 0) {
        s_y0 = __ldg(&box_yx[box * 2]);
        s_x0 = __ldg(&box_yx[box * 2 + 1]);
        s_d = (__ldg(&dec[box * 3]) > 0 ? 1 : 0) |
              (__ldg(&dec[box * 3 + 1]) > 0 ? 2 : 0) |
              (__ldg(&dec[box * 3 + 2]) > 0 ? 4 : 0);
        l_cnt = 0;
    }
    __syncthreads();

    // compact the later boxes (m > n, same batch) that overlap our 32-row strip
    if (tid >= n + 1 && tid < NPER) {
        int mb = b * NPER + tid;
        int ym = __ldg(&box_yx[mb * 2]);
        int xm = __ldg(&box_yx[mb * 2 + 1]);
        int ylo = s_y0 + rbase, yhi = s_y0 + rbase + 32;   // [ylo, yhi)
        bool ovl = (ym < yhi) && (ym + PB > ylo) &&
                   (xm < s_x0 + PB) && (xm + PB > s_x0);
        if (ovl) {
            int idx = atomicAdd(&l_cnt, 1);
            l_y[idx] = ym;
            l_x[idx] = xm;
        }
    }

    // wait for downsample
    if (tid == 0) {
        volatile int* p = &g_sync[0];
        while (*p < DS_BLOCKS) __nanosleep(64);
    }
    __syncthreads();

    int rx = tid / 3;
    int c = tid - 3 * rx;
    int d = s_d;
    int x1 = (d & 2) ? (PB - 1 - rx) : rx;      // thread-fixed
    int xg = s_x0 + rx;
    int cnt = l_cnt;

    for (int r = 0; r < 32; r++) {
        int ry = rbase + r;
        int yg = s_y0 + ry;
        bool skip = false;
        for (int m = 0; m < cnt; m++) {
            if ((unsigned)(yg - l_y[m]) < (unsigned)PB &&
                (unsigned)(xg - l_x[m]) < (unsigned)PB) { skip = true; break; }
        }
        if (skip) continue;
        int y2 = (d & 4) ? (PB - 1 - ry) : ry;
        float val;
        if (d & 1) {
            // sy = x1 (fixed), sx = 127-y2 (row-dep): read transposed for coalescing
            int sx_ = PB - 1 - y2;
            val = g_smallT[(sx_ * PB + x1) * 3 + c];
        } else {
            val = g_small[(y2 * PB + x1) * 3 + c];
        }
        out[((size_t)(b * HW + yg) * HW + xg) * 3 + c] = val;
    }
}

// ---------------------------------------------------------------------------
// Role: streaming copy with coverage-masked stores. Never waits, near-zero ALU.
// ---------------------------------------------------------------------------
__device__ void role_copy(int cb, const float* __restrict__ images,
                          const int* __restrict__ box_yx,
                          float* __restrict__ out) {
    int b = cb >> 8;                     // 256 blocks per image
    int ybase = (cb & 255) * ROWS_PER_CP;
    int tid = threadIdx.x;

    __shared__ unsigned s_cov[ROWS_PER_CP][32];   // 4 rows x 1024 bits

    if (tid < ROWS_PER_CP * 32) ((unsigned*)s_cov)[tid] = 0u;
    __syncthreads();

    // build coverage: 64 threads = (box, row)
    if (tid < NPER * ROWS_PER_CP) {
        int bx_ = tid >> 2;              // box 0..15
        int r = tid & 3;                 // row 0..3
        int boxid = b * NPER + bx_;
        int y0 = __ldg(&box_yx[boxid * 2]);
        if ((unsigned)(ybase + r - y0) < (unsigned)PB) {
            int x0 = __ldg(&box_yx[boxid * 2 + 1]);
            int w0 = x0 >> 5, off = x0 & 31;
            if (off == 0) {
#pragma unroll
                for (int w = 0; w < 4; w++) atomicOr(&s_cov[r][w0 + w], 0xFFFFFFFFu);
            } else {
                atomicOr(&s_cov[r][w0], 0xFFFFFFFFu << off);
#pragma unroll
                for (int w = 1; w < 4; w++) atomicOr(&s_cov[r][w0 + w], 0xFFFFFFFFu);
                atomicOr(&s_cov[r][w0 + 4], 0xFFFFFFFFu >> (32 - off));
            }
        }
    }
    __syncthreads();

    size_t base4 = ((size_t)(b * HW + ybase)) * (HW * 3 / 4);
    const float4* src4 = (const float4*)images + base4;
    float4* dst4 = (float4*)out + base4;

#pragma unroll
    for (int h = 0; h < 2; h++) {
        float4 v[4];
        int cc[4];
#pragma unroll
        for (int k = 0; k < 4; k++) {
            int q = h * 4 + k;
            int row = q >> 1;
            int qq = (q & 1) * THREADS + tid;
            int fo = qq * 4;
            int pa = fo / 3;                       // quad spans px pa, pa+1
            int ca = (s_cov[row][pa >> 5] >> (pa & 31)) & 1;
            int cbit = (s_cov[row][(pa + 1) >> 5] >> ((pa + 1) & 31)) & 1;
            cc[k] = ca | (cbit << 1);
            if (cc[k] != 3)
                v[k] = __ldcs(&src4[(q >> 1) * 768 + (q & 1) * THREADS + tid]);
        }
#pragma unroll
        for (int k = 0; k < 4; k++) {
            int q = h * 4 + k;
            if (cc[k] == 3) continue;              // fully pasted: paste blocks own it
            float4* dp = &dst4[(q >> 1) * 768 + (q & 1) * THREADS + tid];
            if (cc[k] == 0) {
                __stcs(dp, v[k]);
            } else {
                // mixed quad (box edge): store only uncovered floats
                int qq = (q & 1) * THREADS + tid;
                int fo = qq * 4;
                int pa = fo / 3;
                float* df = (float*)dp;
                const float* vf = (const float*)&v[k];
#pragma unroll
                for (int e = 0; e < 4; e++) {
                    int px = (fo + e) / 3;
                    int covered = (px == pa) ? (cc[k] & 1) : ((cc[k] >> 1) & 1);
                    if (!covered) df[e] = vf[e];
                }
            }
        }
    }
}

// ---------------------------------------------------------------------------
// Role: reduce gather partials + bilinear upsample 128->256 + analytic TV grad.
// ---------------------------------------------------------------------------
__device__ __forceinline__ float acc_at(int y, int x, int c) {
    float s = 0.f;
#pragma unroll
    for (int g = 0; g < NGRP; g++) {
        s += g_nr[g][y][x * 3 + c];
        s += g_rt[g][x][y * 3 + c];
    }
    return s;
}

__device__ void role_final(int fb, const float* __restrict__ patch,
                           float* __restrict__ agg) {
    if (threadIdx.x == 0) {
        volatile int* p = &g_sync[1];
        while (*p < GT_BLOCKS) __nanosleep(64);
    }
    __syncthreads();

    int t = fb * THREADS + threadIdx.x;
    int c = t % 3;
    int j = (t / 3) % PHW;
    int i = t / (PHW * 3);

    int ky = i >> 1, y0, y1; float wy0, wy1;
    if (i & 1) { y0 = ky;             y1 = min(ky + 1, PB - 1); wy0 = 0.75f; wy1 = 0.25f; }
    else       { y0 = max(ky - 1, 0); y1 = ky;                  wy0 = 0.25f; wy1 = 0.75f; }
    int kx = j >> 1, x0, x1; float wx0, wx1;
    if (j & 1) { x0 = kx;             x1 = min(kx + 1, PB - 1); wx0 = 0.75f; wx1 = 0.25f; }
    else       { x0 = max(kx - 1, 0); x1 = kx;                  wx0 = 0.25f; wx1 = 0.75f; }

    float v = wy0 * (wx0 * acc_at(y0, x0, c) + wx1 * acc_at(y0, x1, c))
            + wy1 * (wx0 * acc_at(y1, x0, c) + wx1 * acc_at(y1, x1, c));

    float pij = __ldg(&patch[(i * PHW + j) * 3 + c]);
    float a = (j < PHW - 1) ? (pij - __ldg(&patch[(i * PHW + j + 1) * 3 + c])) : 0.f;
    float bb = (i < PHW - 1) ? (pij - __ldg(&patch[((i + 1) * PHW + j) * 3 + c])) : 0.f;
    float g = (a + bb) * rsqrtf(a * a + bb * bb + 1e-12f);
    if (j > 0) {
        float pl = __ldg(&patch[(i * PHW + j - 1) * 3 + c]);
        float al = pl - pij;
        float bl = (i < PHW - 1) ? (pl - __ldg(&patch[((i + 1) * PHW + j - 1) * 3 + c])) : 0.f;
        g -= al * rsqrtf(al * al + bl * bl + 1e-12f);
    }
    if (i > 0) {
        float pu = __ldg(&patch[((i - 1) * PHW + j) * 3 + c]);
        float bu = pu - pij;
        float au = (j < PHW - 1) ? (pu - __ldg(&patch[((i - 1) * PHW + j + 1) * 3 + c])) : 0.f;
        g -= bu * rsqrtf(au * au + bu * bu + 1e-12f);
    }
    agg[t] = v + 0.5f * g;
}

// ---------------------------------------------------------------------------
__global__ void __launch_bounds__(THREADS, 4) k_mega(
        const float* __restrict__ images, const float* __restrict__ grads,
        const float* __restrict__ patch,
        const int* __restrict__ box_yx, const int* __restrict__ dec,
        float* __restrict__ out, float* __restrict__ agg) {
    int bid = blockIdx.x;
    if (bid < DS_BLOCKS) {
        role_downsample(bid, patch);
    } else if (bid < DS_BLOCKS + GT_BLOCKS) {
        role_gather(bid - DS_BLOCKS, grads, box_yx, dec);
    } else if (bid < DS_BLOCKS + GT_BLOCKS + PS_BLOCKS) {
        role_paste(bid - (DS_BLOCKS + GT_BLOCKS), grads, box_yx, dec, out);
    } else if (bid < DS_BLOCKS + GT_BLOCKS + PS_BLOCKS + CP_BLOCKS) {
        role_copy(bid - (DS_BLOCKS + GT_BLOCKS + PS_BLOCKS), images, box_yx, out);
    } else {
        role_final(bid - (DS_BLOCKS + GT_BLOCKS + PS_BLOCKS + CP_BLOCKS), patch, agg);
    }
}

// ---------------------------------------------------------------------------
extern "C" void kernel_launch(void* const* d_in, const int* in_sizes, int n_in,
                              void* d_out, int out_size) {
    const float* images = (const float*)d_in[0];
    const float* grads  = (const float*)d_in[1];
    const float* patch  = (const float*)d_in[2];
    const int*   box_yx = (const int*)d_in[3];
    const int*   dec    = (const int*)d_in[4];

    float* out = (float*)d_out;
    size_t img_elems = (size_t)BIMG * HW * HW * 3;
    float* agg = out + img_elems;

    void* sptr = nullptr;
    cudaGetSymbolAddress(&sptr, g_sync);
    cudaMemsetAsync(sptr, 0, 2 * sizeof(int));

    k_mega<<<TOTAL_BLOCKS, THREADS>>>(images, grads, patch, box_yx, dec, out, agg);
}